// round 12
// baseline (speedup 1.0000x reference)
#include <cuda_runtime.h>
#include <math.h>

// Problem constants (shape-specialized)
#define BB 8
#define CC 3
#define HH 720
#define WW 1280
#define PLANE (HH * WW)          // 921600
#define PLANE_M1 (PLANE - 1)

// Tile config: exact tiling 1280/32=40, 720/40=18
#define TW 32
#define TH 40
#define RPT 5            // rows per thread (8 row-groups * 5 = 40)
#define NTHREADS 256
#define HW2 (TW + 2)     // 34
#define HH2 (TH + 2)     // 42
#define HALO (HH2 * HW2) // 1428
#define NBLOCKS ((WW / TW) * (HH / TH) * BB)   // 40*18*8 = 5760

// halo idx step geometry: 256 = 7*34 + 18
#define DLO (7 * WW + 18)     // step of linear offset per 256 elements
#define CLO (WW - HW2)        // extra when hc wraps

#define ALPHA_C 0.85f
#define C1P (81.0f * 0.0001f)   // 81 * C1
#define C2P (81.0f * 0.0009f)   // 81 * C2

typedef unsigned long long ull;

__device__ __forceinline__ ull add2(ull a, ull b) {
    ull d; asm("add.rn.f32x2 %0, %1, %2;" : "=l"(d) : "l"(a), "l"(b)); return d;
}
__device__ __forceinline__ ull mul2(ull a, ull b) {
    ull d; asm("mul.rn.f32x2 %0, %1, %2;" : "=l"(d) : "l"(a), "l"(b)); return d;
}
__device__ __forceinline__ ull fma2(ull a, ull b, ull c) {
    ull d; asm("fma.rn.f32x2 %0, %1, %2, %3;" : "=l"(d) : "l"(a), "l"(b), "l"(c)); return d;
}
__device__ __forceinline__ float2 up2(ull v) {
    float2 f; asm("mov.b64 {%0, %1}, %2;" : "=f"(f.x), "=f"(f.y) : "l"(v)); return f;
}
__device__ __forceinline__ ull pk2(float x, float y) {
    ull v; asm("mov.b64 %0, {%1, %2};" : "=l"(v) : "f"(x), "f"(y)); return v;
}

__device__ double g_acc[2];          // [0]=sum(photo*valid), [1]=sum(valid)
__device__ unsigned int g_count;

struct HS2 { ull s1; ull sq; float xy; float2 ctr; };

__device__ __forceinline__ HS2 hsum_row(const ull* __restrict__ p) {
    HS2 h;
    ull a = p[0], b = p[1], c = p[2];
    h.s1 = add2(a, add2(b, c));                 // (Sx, Sy)
    h.sq = fma2(a, a, fma2(b, b, mul2(c, c)));  // (Sxx, Syy)
    float2 fa = up2(a), fb = up2(b), fc = up2(c);
    h.xy = fmaf(fa.x, fa.y, fmaf(fb.x, fb.y, fc.x * fc.y));
    h.ctr = fb;                                 // center column value
    return h;
}

__global__ __launch_bounds__(NTHREADS, 8)
void pl_main_kernel(const float* __restrict__ disp,
                    const float* __restrict__ left,
                    const float* __restrict__ right,
                    float* __restrict__ out) {
    __shared__ int2          s_g[HALO];   // (o0, fw-bits) packed: one LDS.64 per access
    __shared__ ull           s_xy[HALO];  // (left, warped) packed f32x2, current channel
    __shared__ unsigned char s_vd[HALO];  // validity of raw x_sample (exact ref test)
    __shared__ float         s_red[2][NTHREADS / 32];

    const int b  = blockIdx.z;
    const int w0 = blockIdx.x * TW;
    const int h0 = blockIdx.y * TH;
    const int tid = threadIdx.x;
    const int tx = tid & 31;
    const int tg = tid >> 5;
    const bool interior = (blockIdx.x > 0) && (blockIdx.x < (WW / TW) - 1) &&
                          (blockIdx.y > 0) && (blockIdx.y < (HH / TH) - 1);

    const int hr0 = tid / HW2;
    const int hc0 = tid - hr0 * HW2;

    const size_t plane = (size_t)PLANE;
    const float* dplane = disp  + (size_t)b * plane;
    const float* lplane = left  + (size_t)b * CC * plane;
    const float* rplane = right + (size_t)b * CC * plane;

    // ---- Pass 0: geometry + validity + channel-0 fill, fused ----
    if (interior) {
        int   hc  = hc0;
        int   lo  = (h0 - 1 + hr0) * WW + (w0 - 1 + hc0);
        float fww = (float)(w0 - 1 + hc0);
        for (int idx = tid; idx < HALO; idx += NTHREADS) {
            float d   = dplane[lo];
            float xsr = fww - d;
            float xs  = fminf(fmaxf(xsr, 0.f), (float)(WW - 1));
            float x0f = floorf(xs);
            float fw  = xs - x0f;
            int   ww  = __float2int_rn(fww);
            int   o0  = (lo - ww) + (int)x0f;
            float x  = lplane[lo];
            float g0 = rplane[o0];
            float g1 = rplane[min(o0 + 1, PLANE_M1)];
            float y  = fmaf(fw, g1 - g0, g0);
            s_g[idx]  = make_int2(o0, __float_as_int(fw));
            s_vd[idx] = (xsr > 0.f && xsr < (float)(WW - 1)) ? 1 : 0;
            s_xy[idx] = pk2(x, y);
            hc += 18; lo += DLO; fww += 18.f;
            if (hc >= HW2) { hc -= HW2; lo += CLO; fww -= (float)HW2; }
        }
    } else {
        int hr = hr0, hc = hc0;
        for (int idx = tid; idx < HALO; idx += NTHREADS) {
            int hh = h0 - 1 + hr, ww = w0 - 1 + hc;
            int o0 = 0;
            float fw = 0.f, x = 0.f, y = 0.f;
            unsigned char vd = 0;
            if (hh >= 0 && hh < HH && ww >= 0 && ww < WW) {
                int rowbase = hh * WW;
                float xsr = (float)ww - dplane[rowbase + ww];
                vd = (xsr > 0.f && xsr < (float)(WW - 1)) ? 1 : 0;
                float xs = fminf(fmaxf(xsr, 0.f), (float)(WW - 1));
                float x0f = floorf(xs);
                fw = xs - x0f;
                o0 = rowbase + (int)x0f;
                x = lplane[rowbase + ww];
                float g0 = rplane[o0];
                float g1 = rplane[min(o0 + 1, PLANE_M1)];
                y = fmaf(fw, g1 - g0, g0);
            }
            s_g[idx]  = make_int2(o0, __float_as_int(fw));
            s_vd[idx] = vd;
            s_xy[idx] = pk2(x, y);
            hr += 7; hc += 18;
            if (hc >= HW2) { hc -= HW2; hr += 1; }
        }
    }
    __syncthreads();

    const int base = tg * RPT;

    // ---- validity mask: precomputed exact test on raw x_sample ----
    unsigned int vmask = 0u;
    {
        int cidx = (base + 1) * HW2 + tx + 1;
#pragma unroll
        for (int k = 0; k < RPT; k++, cidx += HW2) {
            if (s_vd[cidx]) vmask |= (1u << k);
        }
    }
    float vsum = (float)__popc(vmask);
    float psum = 0.f;

    // ---- pooling over current s_xy contents ----
    auto pool = [&]() {
        const ull* p = &s_xy[base * HW2 + tx];
        HS2 a0 = hsum_row(p); p += HW2;
        HS2 a1 = hsum_row(p); p += HW2;
#pragma unroll
        for (int k = 0; k < RPT; k++) {
            HS2 a2 = hsum_row(p); p += HW2;

            ull S1 = add2(a0.s1, add2(a1.s1, a2.s1));  // (Sx, Sy)
            ull SQ = add2(a0.sq, add2(a1.sq, a2.sq));  // (Sxx, Syy)
            float Sxy = a0.xy + a1.xy + a2.xy;

            ull M = mul2(S1, S1);                      // (A2, B2)
            float2 ab = up2(S1);
            float2 m  = up2(M);
            float2 q  = up2(SQ);
            float A = ab.x, B = ab.y;
            float A2 = m.x, B2 = m.y;
            float AB = A * B;
            float sgx = fmaxf(fmaf(9.f, q.x, -A2), 0.f);
            float sgy = fmaxf(fmaf(9.f, q.y, -B2), 0.f);
            float n1 = fmaf(2.f, AB, C1P);
            float n2 = fmaf(18.f, Sxy, fmaf(-2.f, AB, C2P));
            float d1 = A2 + B2 + C1P;
            float d2 = sgx + sgy + C2P;
            float r  = __fdividef(n1 * n2, d1 * d2);
            float ss = fmaf(-0.5f, r, 0.5f);
            ss = fminf(fmaxf(ss, 0.f), 1.f);

            float l1 = fabsf(a1.ctr.x - a1.ctr.y);     // center pixel from rolling hsum

            float contrib = fmaf(ALPHA_C * (1.f / 3.f), ss,
                                 (1.f - ALPHA_C) * (1.f / 3.f) * l1);
            float vf = (float)((vmask >> k) & 1u);
            psum = fmaf(contrib, vf, psum);

            a0 = a1;
            a1 = a2;
        }
    };

    pool();   // channel 0

    for (int c = 1; c < CC; c++) {
        lplane += plane;
        rplane += plane;
        __syncthreads();   // pooling of previous channel done reading s_xy

        if (interior) {
            int hc = hc0;
            int lo = (h0 - 1 + hr0) * WW + (w0 - 1 + hc0);
            for (int idx = tid; idx < HALO; idx += NTHREADS) {
                int2 g = s_g[idx];
                int   o0 = g.x;
                float fw = __int_as_float(g.y);
                float x  = lplane[lo];
                float g0 = rplane[o0];
                float g1 = rplane[min(o0 + 1, PLANE_M1)];
                s_xy[idx] = pk2(x, fmaf(fw, g1 - g0, g0));
                hc += 18; lo += DLO;
                if (hc >= HW2) { hc -= HW2; lo += CLO; }
            }
        } else {
            int hr = hr0, hc = hc0;
            for (int idx = tid; idx < HALO; idx += NTHREADS) {
                int hh = h0 - 1 + hr, ww = w0 - 1 + hc;
                float x = 0.f, y = 0.f;
                if (hh >= 0 && hh < HH && ww >= 0 && ww < WW) {
                    int2 g = s_g[idx];
                    int   o0 = g.x;
                    float fw = __int_as_float(g.y);
                    x = lplane[hh * WW + ww];
                    float g0 = rplane[o0];
                    float g1 = rplane[min(o0 + 1, PLANE_M1)];
                    y = fmaf(fw, g1 - g0, g0);
                }
                s_xy[idx] = pk2(x, y);
                hr += 7; hc += 18;
                if (hc >= HW2) { hc -= HW2; hr += 1; }
            }
        }
        __syncthreads();

        pool();
    }

    // ---- block reduction ----
#pragma unroll
    for (int off = 16; off > 0; off >>= 1) {
        psum += __shfl_down_sync(0xFFFFFFFFu, psum, off);
        vsum += __shfl_down_sync(0xFFFFFFFFu, vsum, off);
    }
    if (tx == 0) {
        s_red[0][tg] = psum;
        s_red[1][tg] = vsum;
    }
    __syncthreads();
    if (tid == 0) {
        float p = 0.f, v = 0.f;
#pragma unroll
        for (int i = 0; i < NTHREADS / 32; i++) {
            p += s_red[0][i];
            v += s_red[1][i];
        }
        atomicAdd(&g_acc[0], (double)p);
        atomicAdd(&g_acc[1], (double)v);
        __threadfence();
        unsigned int done = atomicAdd(&g_count, 1u);
        if (done == NBLOCKS - 1) {
            // last block: finalize + reset for next graph replay
            double P = atomicAdd(&g_acc[0], 0.0);
            double V = atomicAdd(&g_acc[1], 0.0);
            out[0] = (float)(P / fmax(V, 1.0));
            g_acc[0] = 0.0;
            g_acc[1] = 0.0;
            g_count = 0u;
            __threadfence();
        }
    }
}

extern "C" void kernel_launch(void* const* d_in, const int* in_sizes, int n_in,
                              void* d_out, int out_size) {
    const float* disp  = (const float*)d_in[0];
    const float* left  = (const float*)d_in[1];
    const float* right = (const float*)d_in[2];
    float* out = (float*)d_out;

    dim3 grid(WW / TW, HH / TH, BB);   // 40 x 18 x 8 = 5760
    pl_main_kernel<<<grid, NTHREADS>>>(disp, left, right, out);
}

// round 13
// speedup vs baseline: 1.1868x; 1.1868x over previous
#include <cuda_runtime.h>
#include <math.h>

// Problem constants (shape-specialized)
#define BB 8
#define CC 3
#define HH 720
#define WW 1280

// Tile config: exact tiling 1280/32=40, 720/40=18
#define TW 32
#define TH 40
#define RPT 5            // rows per thread (8 row-groups * 5 = 40)
#define NTHREADS 256
#define HW2 (TW + 2)     // 34
#define HH2 (TH + 2)     // 42
#define HALO (HH2 * HW2) // 1428
#define NBLOCKS ((WW / TW) * (HH / TH) * BB)   // 40*18*8 = 5760

// halo idx step geometry: 256 = 7*34 + 18
#define DLO (7 * WW + 18)     // step of linear offset per 256 elements
#define CLO (WW - HW2)        // extra when hc wraps

#define ALPHA_C 0.85f
#define C1P (81.0f * 0.0001f)   // 81 * C1
#define C2P (81.0f * 0.0009f)   // 81 * C2

typedef unsigned long long ull;

__device__ __forceinline__ ull add2(ull a, ull b) {
    ull d; asm("add.rn.f32x2 %0, %1, %2;" : "=l"(d) : "l"(a), "l"(b)); return d;
}
__device__ __forceinline__ ull mul2(ull a, ull b) {
    ull d; asm("mul.rn.f32x2 %0, %1, %2;" : "=l"(d) : "l"(a), "l"(b)); return d;
}
__device__ __forceinline__ ull fma2(ull a, ull b, ull c) {
    ull d; asm("fma.rn.f32x2 %0, %1, %2, %3;" : "=l"(d) : "l"(a), "l"(b), "l"(c)); return d;
}
__device__ __forceinline__ float2 up2(ull v) {
    float2 f; asm("mov.b64 {%0, %1}, %2;" : "=f"(f.x), "=f"(f.y) : "l"(v)); return f;
}
__device__ __forceinline__ ull pk2(float x, float y) {
    ull v; asm("mov.b64 %0, {%1, %2};" : "=l"(v) : "f"(x), "f"(y)); return v;
}

__device__ double g_acc[2];          // [0]=sum(photo*valid), [1]=sum(valid)
__device__ unsigned int g_count;

struct HS2 { ull s1; ull sq; float xy; float2 ctr; };

__device__ __forceinline__ HS2 hsum_row(const ull* __restrict__ p) {
    HS2 h;
    ull a = p[0], b = p[1], c = p[2];
    h.s1 = add2(a, add2(b, c));                 // (Sx, Sy)
    h.sq = fma2(a, a, fma2(b, b, mul2(c, c)));  // (Sxx, Syy)
    float2 fa = up2(a), fb = up2(b), fc = up2(c);
    h.xy = fmaf(fa.x, fa.y, fmaf(fb.x, fb.y, fc.x * fc.y));
    h.ctr = fb;                                 // center column value
    return h;
}

__global__ __launch_bounds__(NTHREADS, 8)
void pl_main_kernel(const float* __restrict__ disp,
                    const float* __restrict__ left,
                    const float* __restrict__ right,
                    float* __restrict__ out) {
    __shared__ int2  s_g[HALO];     // (o0, fw-bits) packed: one LDS.64 per access
    __shared__ ull   s_xy[HALO];    // (left, warped) packed f32x2, current channel
    __shared__ float s_red[2][NTHREADS / 32];

    const int b  = blockIdx.z;
    const int w0 = blockIdx.x * TW;
    const int h0 = blockIdx.y * TH;
    const int tid = threadIdx.x;
    const int tx = tid & 31;
    const int tg = tid >> 5;
    const bool interior = (blockIdx.x > 0) && (blockIdx.x < (WW / TW) - 1) &&
                          (blockIdx.y > 0) && (blockIdx.y < (HH / TH) - 1);

    const int hr0 = tid / HW2;
    const int hc0 = tid - hr0 * HW2;

    const size_t plane = (size_t)HH * WW;
    const float* dplane = disp  + (size_t)b * plane;
    const float* lplane = left  + (size_t)b * CC * plane;
    const float* rplane = right + (size_t)b * CC * plane;

    // ---- Pass 0: geometry + channel-0 fill, fused ----
    if (interior) {
        int   hc  = hc0;
        int   lo  = (h0 - 1 + hr0) * WW + (w0 - 1 + hc0);
        float fww = (float)(w0 - 1 + hc0);
        for (int idx = tid; idx < HALO; idx += NTHREADS) {
            float d  = dplane[lo];
            float xs = fminf(fmaxf(fww - d, 0.f), (float)(WW - 1));
            float x0f = floorf(xs);
            float fw  = xs - x0f;
            int   ww  = __float2int_rn(fww);
            int   o0  = (lo - ww) + (int)x0f;
            float x  = lplane[lo];
            float g0 = rplane[o0];
            float g1 = rplane[o0 + (fw > 0.f ? 1 : 0)];
            float y  = fmaf(fw, g1 - g0, g0);
            s_g[idx]  = make_int2(o0, __float_as_int(fw));
            s_xy[idx] = pk2(x, y);
            hc += 18; lo += DLO; fww += 18.f;
            if (hc >= HW2) { hc -= HW2; lo += CLO; fww -= (float)HW2; }
        }
    } else {
        int hr = hr0, hc = hc0;
        for (int idx = tid; idx < HALO; idx += NTHREADS) {
            int hh = h0 - 1 + hr, ww = w0 - 1 + hc;
            int o0 = 0;
            float fw = 0.f, x = 0.f, y = 0.f;
            if (hh >= 0 && hh < HH && ww >= 0 && ww < WW) {
                int rowbase = hh * WW;
                float xsr = (float)ww - dplane[rowbase + ww];
                float xs = fminf(fmaxf(xsr, 0.f), (float)(WW - 1));
                float x0f = floorf(xs);
                fw = xs - x0f;
                o0 = rowbase + (int)x0f;
                x = lplane[rowbase + ww];
                float g0 = rplane[o0];
                float g1 = rplane[o0 + (fw > 0.f ? 1 : 0)];
                y = fmaf(fw, g1 - g0, g0);
            }
            s_g[idx]  = make_int2(o0, __float_as_int(fw));
            s_xy[idx] = pk2(x, y);
            hr += 7; hc += 18;
            if (hc >= HW2) { hc -= HW2; hr += 1; }
        }
    }
    __syncthreads();

    const int base = tg * RPT;

    // ---- validity mask: valid <=> (i0 > 0 || fw > 0) && (i0 < W-1) ----
    unsigned int vmask = 0u;
    {
        int cidx = (base + 1) * HW2 + tx + 1;
        int hwbase = (h0 + base) * WW;
#pragma unroll
        for (int k = 0; k < RPT; k++, cidx += HW2, hwbase += WW) {
            int2 g = s_g[cidx];
            int i0 = g.x - hwbase;
            float fw = __int_as_float(g.y);
            if ((i0 > 0 || fw > 0.f) && i0 < WW - 1) vmask |= (1u << k);
        }
    }
    float vsum = (float)__popc(vmask);
    float psum = 0.f;

    // ---- pooling over current s_xy contents ----
    auto pool = [&]() {
        const ull* p = &s_xy[base * HW2 + tx];
        HS2 a0 = hsum_row(p); p += HW2;
        HS2 a1 = hsum_row(p); p += HW2;
#pragma unroll
        for (int k = 0; k < RPT; k++) {
            HS2 a2 = hsum_row(p); p += HW2;

            ull S1 = add2(a0.s1, add2(a1.s1, a2.s1));  // (Sx, Sy)
            ull SQ = add2(a0.sq, add2(a1.sq, a2.sq));  // (Sxx, Syy)
            float Sxy = a0.xy + a1.xy + a2.xy;

            ull M = mul2(S1, S1);                      // (A2, B2)
            float2 ab = up2(S1);
            float2 m  = up2(M);
            float2 q  = up2(SQ);
            float A = ab.x, B = ab.y;
            float A2 = m.x, B2 = m.y;
            float AB = A * B;
            float sgx = fmaxf(fmaf(9.f, q.x, -A2), 0.f);
            float sgy = fmaxf(fmaf(9.f, q.y, -B2), 0.f);
            float n1 = fmaf(2.f, AB, C1P);
            float n2 = fmaf(18.f, Sxy, fmaf(-2.f, AB, C2P));
            float d1 = A2 + B2 + C1P;
            float d2 = sgx + sgy + C2P;
            float r  = __fdividef(n1 * n2, d1 * d2);
            float ss = fmaf(-0.5f, r, 0.5f);
            ss = fminf(fmaxf(ss, 0.f), 1.f);

            float l1 = fabsf(a1.ctr.x - a1.ctr.y);     // center pixel from rolling hsum

            float contrib = fmaf(ALPHA_C * (1.f / 3.f), ss,
                                 (1.f - ALPHA_C) * (1.f / 3.f) * l1);
            float vf = (float)((vmask >> k) & 1u);
            psum = fmaf(contrib, vf, psum);

            a0 = a1;
            a1 = a2;
        }
    };

    pool();   // channel 0

    for (int c = 1; c < CC; c++) {
        lplane += plane;
        rplane += plane;
        __syncthreads();   // pooling of previous channel done reading s_xy

        if (interior) {
            int hc = hc0;
            int lo = (h0 - 1 + hr0) * WW + (w0 - 1 + hc0);
            for (int idx = tid; idx < HALO; idx += NTHREADS) {
                int2 g = s_g[idx];
                int   o0 = g.x;
                float fw = __int_as_float(g.y);
                float x  = lplane[lo];
                float g0 = rplane[o0];
                float g1 = rplane[o0 + (fw > 0.f ? 1 : 0)];
                s_xy[idx] = pk2(x, fmaf(fw, g1 - g0, g0));
                hc += 18; lo += DLO;
                if (hc >= HW2) { hc -= HW2; lo += CLO; }
            }
        } else {
            int hr = hr0, hc = hc0;
            for (int idx = tid; idx < HALO; idx += NTHREADS) {
                int hh = h0 - 1 + hr, ww = w0 - 1 + hc;
                float x = 0.f, y = 0.f;
                if (hh >= 0 && hh < HH && ww >= 0 && ww < WW) {
                    int2 g = s_g[idx];
                    int   o0 = g.x;
                    float fw = __int_as_float(g.y);
                    x = lplane[hh * WW + ww];
                    float g0 = rplane[o0];
                    float g1 = rplane[o0 + (fw > 0.f ? 1 : 0)];
                    y = fmaf(fw, g1 - g0, g0);
                }
                s_xy[idx] = pk2(x, y);
                hr += 7; hc += 18;
                if (hc >= HW2) { hc -= HW2; hr += 1; }
            }
        }
        __syncthreads();

        pool();
    }

    // ---- block reduction ----
#pragma unroll
    for (int off = 16; off > 0; off >>= 1) {
        psum += __shfl_down_sync(0xFFFFFFFFu, psum, off);
        vsum += __shfl_down_sync(0xFFFFFFFFu, vsum, off);
    }
    if (tx == 0) {
        s_red[0][tg] = psum;
        s_red[1][tg] = vsum;
    }
    __syncthreads();
    if (tid == 0) {
        float p = 0.f, v = 0.f;
#pragma unroll
        for (int i = 0; i < NTHREADS / 32; i++) {
            p += s_red[0][i];
            v += s_red[1][i];
        }
        atomicAdd(&g_acc[0], (double)p);
        atomicAdd(&g_acc[1], (double)v);
        __threadfence();
        unsigned int done = atomicAdd(&g_count, 1u);
        if (done == NBLOCKS - 1) {
            // last block: finalize + reset for next graph replay
            double P = atomicAdd(&g_acc[0], 0.0);
            double V = atomicAdd(&g_acc[1], 0.0);
            out[0] = (float)(P / fmax(V, 1.0));
            g_acc[0] = 0.0;
            g_acc[1] = 0.0;
            g_count = 0u;
            __threadfence();
        }
    }
}

extern "C" void kernel_launch(void* const* d_in, const int* in_sizes, int n_in,
                              void* d_out, int out_size) {
    const float* disp  = (const float*)d_in[0];
    const float* left  = (const float*)d_in[1];
    const float* right = (const float*)d_in[2];
    float* out = (float*)d_out;

    dim3 grid(WW / TW, HH / TH, BB);   // 40 x 18 x 8 = 5760
    pl_main_kernel<<<grid, NTHREADS>>>(disp, left, right, out);
}